// round 1
// baseline (speedup 1.0000x reference)
#include <cuda_runtime.h>
#include <cuda_bf16.h>
#include <cstdint>

#define N_NODES 50000
#define F_NODE  256
#define F_HEDGE 128

// Scratch (device globals: allocation-free per harness rules)
__device__ float g_A[(size_t)N_NODES * F_NODE];   // segsum(conv * x[s])       [50000,256]
__device__ float g_B[(size_t)N_NODES * F_HEDGE];  // segsum(conv2 * h[s2])     [50000,128]
__device__ float g_c[N_NODES];                    // segsum(conv)
__device__ float g_c2[N_NODES];                   // segsum(conv2)

// ---------------------------------------------------------------------------
// f32x2 packed helpers (Blackwell FFMA2)
// ---------------------------------------------------------------------------
__device__ __forceinline__ unsigned long long pk2(float lo, float hi) {
    unsigned long long r;
    asm("mov.b64 %0, {%1, %2};" : "=l"(r) : "f"(lo), "f"(hi));
    return r;
}
__device__ __forceinline__ void fma2(unsigned long long& d,
                                     unsigned long long a,
                                     unsigned long long b) {
    asm("fma.rn.f32x2 %0, %1, %2, %0;" : "+l"(d) : "l"(a), "l"(b));
}
__device__ __forceinline__ float2 unpk2(unsigned long long v) {
    float2 f;
    asm("mov.b64 {%0, %1}, %2;" : "=f"(f.x), "=f"(f.y) : "l"(v));
    return f;
}

// ---------------------------------------------------------------------------
// Zero scratch
// ---------------------------------------------------------------------------
__global__ void zero_all() {
    size_t stride = (size_t)gridDim.x * blockDim.x;
    size_t tid = (size_t)blockIdx.x * blockDim.x + threadIdx.x;
    float4* pa = reinterpret_cast<float4*>(g_A);
    const size_t na = (size_t)N_NODES * F_NODE / 4;
    for (size_t i = tid; i < na; i += stride) pa[i] = make_float4(0.f, 0.f, 0.f, 0.f);
    float4* pb = reinterpret_cast<float4*>(g_B);
    const size_t nb = (size_t)N_NODES * F_HEDGE / 4;
    for (size_t i = tid; i < nb; i += stride) pb[i] = make_float4(0.f, 0.f, 0.f, 0.f);
    for (size_t i = tid; i < N_NODES; i += stride) { g_c[i] = 0.f; g_c2[i] = 0.f; }
}

// ---------------------------------------------------------------------------
// Segmented scatter: out[r] += conv_e * feat[s_e], csum[r] += conv_e
// Receivers sorted -> register-accumulate runs, flush one atomicAdd per run.
// Block = 256 threads = (256/G) groups; each group of G = F/4 threads covers
// all F columns (float4/thread) and processes EPG consecutive edges.
// ---------------------------------------------------------------------------
template <int F, int EPG>
__global__ __launch_bounds__(256) void scatter_seg(
    const float* __restrict__ feat,
    const int*   __restrict__ send,
    const int*   __restrict__ recv,
    const float* __restrict__ conv,
    int nE)
{
    constexpr int G  = F / 4;       // threads per group
    constexpr int NG = 256 / G;     // groups per block
    constexpr int SPAN = NG * EPG;  // edges per block

    __shared__ int   sh_s[SPAN];
    __shared__ int   sh_r[SPAN];
    __shared__ float sh_c[SPAN];

    float* outp = (F == F_NODE) ? g_A : g_B;
    float* csum = (F == F_NODE) ? g_c : g_c2;

    const int tid = threadIdx.x;
    const int blockBase = blockIdx.x * SPAN;
    int cnt = nE - blockBase;
    if (cnt > SPAN) cnt = SPAN;

    for (int i = tid; i < cnt; i += 256) {
        sh_s[i] = send[blockBase + i];
        sh_r[i] = recv[blockBase + i];
        sh_c[i] = conv[blockBase + i];
    }
    __syncthreads();

    const int g    = tid / G;
    const int lane = tid % G;
    const int e0 = g * EPG;
    int e1 = e0 + EPG;
    if (e1 > cnt) e1 = cnt;
    if (e0 >= e1) return;

    float4 acc = make_float4(0.f, 0.f, 0.f, 0.f);
    float  accc = 0.f;
    int cur = sh_r[e0];

    // one-deep prefetch of the gathered row
    float4 v = *reinterpret_cast<const float4*>(feat + (size_t)sh_s[e0] * F + lane * 4);

    for (int e = e0; e < e1; ++e) {
        float4 vcur = v;
        if (e + 1 < e1)
            v = *reinterpret_cast<const float4*>(feat + (size_t)sh_s[e + 1] * F + lane * 4);
        int r = sh_r[e];
        if (r != cur) {
            float* o = outp + (size_t)cur * F + lane * 4;
            atomicAdd(o + 0, acc.x); atomicAdd(o + 1, acc.y);
            atomicAdd(o + 2, acc.z); atomicAdd(o + 3, acc.w);
            acc = make_float4(0.f, 0.f, 0.f, 0.f);
            if (lane == 0) { atomicAdd(csum + cur, accc); accc = 0.f; }
            cur = r;
        }
        float cv = sh_c[e];
        acc.x += cv * vcur.x; acc.y += cv * vcur.y;
        acc.z += cv * vcur.z; acc.w += cv * vcur.w;
        if (lane == 0) accc += cv;
    }
    float* o = outp + (size_t)cur * F + lane * 4;
    atomicAdd(o + 0, acc.x); atomicAdd(o + 1, acc.y);
    atomicAdd(o + 2, acc.z); atomicAdd(o + 3, acc.w);
    if (lane == 0) atomicAdd(csum + cur, accc);
}

// ---------------------------------------------------------------------------
// Fused dual-GEMM + bias + Hadamard combine:
//   out = (A @ Wm + c (x) bm) * (B @ Ws + c2 (x) bs)
// Tile: BM=64 rows x BN=64 cols, BK=32, 256 threads (16x16), TM=TN=4,
// f32x2 packed FMA inner product.
// ---------------------------------------------------------------------------
#define BM 64
#define BN 64
#define BK 32

__global__ __launch_bounds__(256) void gemm_combine(
    const float* __restrict__ Wm, const float* __restrict__ bm,
    const float* __restrict__ Wsc, const float* __restrict__ bs,
    float* __restrict__ out)
{
    __shared__ float sA[BM][BK + 1];   // 64 x 33
    __shared__ float sW[BK][BN + 2];   // 32 x 66

    const int tid = threadIdx.x;
    const int tx = tid % 16;           // output cols: tx*4 .. tx*4+3
    const int ty = tid / 16;           // output rows: ty*4 .. ty*4+3
    const int row0 = blockIdx.x * BM;
    const int n0   = blockIdx.y * BN;

    unsigned long long accM[4][2], accS[4][2];
#pragma unroll
    for (int i = 0; i < 4; ++i) { accM[i][0] = 0ull; accM[i][1] = 0ull;
                                  accS[i][0] = 0ull; accS[i][1] = 0ull; }

    // ---- Phase 1: msg GEMM, K = 256 over g_A ----
    for (int k0 = 0; k0 < F_NODE; k0 += BK) {
        for (int l = tid; l < BM * BK; l += 256) {
            int m = l / BK, k = l % BK;
            int r = row0 + m;
            sA[m][k] = (r < N_NODES) ? g_A[(size_t)r * F_NODE + k0 + k] : 0.f;
        }
        for (int l = tid; l < BK * BN; l += 256) {
            int k = l / BN, n = l % BN;
            sW[k][n] = Wm[(size_t)(k0 + k) * 256 + n0 + n];
        }
        __syncthreads();
#pragma unroll
        for (int kk = 0; kk < BK; ++kk) {
            float2 b01 = *reinterpret_cast<const float2*>(&sW[kk][tx * 4]);
            float2 b23 = *reinterpret_cast<const float2*>(&sW[kk][tx * 4 + 2]);
            unsigned long long pb0 = pk2(b01.x, b01.y);
            unsigned long long pb1 = pk2(b23.x, b23.y);
#pragma unroll
            for (int i = 0; i < 4; ++i) {
                float a = sA[ty * 4 + i][kk];
                unsigned long long pa = pk2(a, a);
                fma2(accM[i][0], pa, pb0);
                fma2(accM[i][1], pa, pb1);
            }
        }
        __syncthreads();
    }

    // ---- Phase 2: scale GEMM, K = 128 over g_B ----
    for (int k0 = 0; k0 < F_HEDGE; k0 += BK) {
        for (int l = tid; l < BM * BK; l += 256) {
            int m = l / BK, k = l % BK;
            int r = row0 + m;
            sA[m][k] = (r < N_NODES) ? g_B[(size_t)r * F_HEDGE + k0 + k] : 0.f;
        }
        for (int l = tid; l < BK * BN; l += 256) {
            int k = l / BN, n = l % BN;
            sW[k][n] = Wsc[(size_t)(k0 + k) * 256 + n0 + n];
        }
        __syncthreads();
#pragma unroll
        for (int kk = 0; kk < BK; ++kk) {
            float2 b01 = *reinterpret_cast<const float2*>(&sW[kk][tx * 4]);
            float2 b23 = *reinterpret_cast<const float2*>(&sW[kk][tx * 4 + 2]);
            unsigned long long pb0 = pk2(b01.x, b01.y);
            unsigned long long pb1 = pk2(b23.x, b23.y);
#pragma unroll
            for (int i = 0; i < 4; ++i) {
                float a = sA[ty * 4 + i][kk];
                unsigned long long pa = pk2(a, a);
                fma2(accS[i][0], pa, pb0);
                fma2(accS[i][1], pa, pb1);
            }
        }
        __syncthreads();
    }

    // ---- Epilogue: bias outer products + Hadamard ----
    const int n = n0 + tx * 4;
    float bmv0 = bm[n], bmv1 = bm[n + 1], bmv2 = bm[n + 2], bmv3 = bm[n + 3];
    float bsv0 = bs[n], bsv1 = bs[n + 1], bsv2 = bs[n + 2], bsv3 = bs[n + 3];

#pragma unroll
    for (int i = 0; i < 4; ++i) {
        int r = row0 + ty * 4 + i;
        if (r >= N_NODES) continue;
        float c1 = g_c[r];
        float c2v = g_c2[r];
        float2 m01 = unpk2(accM[i][0]), m23 = unpk2(accM[i][1]);
        float2 s01 = unpk2(accS[i][0]), s23 = unpk2(accS[i][1]);
        float4 o;
        o.x = (m01.x + c1 * bmv0) * (s01.x + c2v * bsv0);
        o.y = (m01.y + c1 * bmv1) * (s01.y + c2v * bsv1);
        o.z = (m23.x + c1 * bmv2) * (s23.x + c2v * bsv2);
        o.w = (m23.y + c1 * bmv3) * (s23.y + c2v * bsv3);
        *reinterpret_cast<float4*>(out + (size_t)r * 256 + n) = o;
    }
}

// ---------------------------------------------------------------------------
extern "C" void kernel_launch(void* const* d_in, const int* in_sizes, int n_in,
                              void* d_out, int out_size)
{
    const float* node_features  = (const float*)d_in[0];
    const float* hedge_features = (const float*)d_in[1];
    const int*   node_senders   = (const int*)d_in[2];
    const int*   node_receivers = (const int*)d_in[3];
    const float* node_conv      = (const float*)d_in[4];
    const int*   h_senders      = (const int*)d_in[5];
    const int*   h_receivers    = (const int*)d_in[6];
    const float* h_conv         = (const float*)d_in[7];
    const float* W_msg          = (const float*)d_in[8];
    const float* b_msg          = (const float*)d_in[9];
    const float* W_scale        = (const float*)d_in[10];
    const float* b_scale        = (const float*)d_in[11];
    float* out = (float*)d_out;

    const int nE  = in_sizes[2];   // 800000
    const int nE2 = in_sizes[5];   // 400000

    zero_all<<<1024, 256>>>();

    // node->node: F=256, 4 groups x 128 edges = 512 edges/block
    scatter_seg<256, 128><<<(nE + 511) / 512, 256>>>(
        node_features, node_senders, node_receivers, node_conv, nE);

    // hedge->node: F=128, 8 groups x 128 edges = 1024 edges/block
    scatter_seg<128, 128><<<(nE2 + 1023) / 1024, 256>>>(
        hedge_features, h_senders, h_receivers, h_conv, nE2);

    dim3 grid((N_NODES + BM - 1) / BM, 256 / BN);
    gemm_combine<<<grid, 256>>>(W_msg, b_msg, W_scale, b_scale, out);
}

// round 5
// speedup vs baseline: 1.6952x; 1.6952x over previous
#include <cuda_runtime.h>
#include <cuda_bf16.h>
#include <cstdint>

#define N_NODES 50000
#define F_NODE  256
#define F_HEDGE 128

// ---------------- scratch (device globals; allocation-free) ----------------
__device__ float g_A[(size_t)N_NODES * F_NODE];   // segsum(conv * x[s])
__device__ float g_B[(size_t)N_NODES * F_HEDGE];  // segsum(conv2 * h[s2])
__device__ float g_c[N_NODES];                    // segsum(conv)
__device__ float g_c2[N_NODES];                   // segsum(conv2)
__device__ float g_M[(size_t)N_NODES * 256];      // GEMM1 result (msg branch)
// W transposed to [n][k], split hi/lo bf16
__device__ __nv_bfloat16 g_Wm_hi[256 * 256];
__device__ __nv_bfloat16 g_Wm_lo[256 * 256];
__device__ __nv_bfloat16 g_Ws_hi[256 * 128];
__device__ __nv_bfloat16 g_Ws_lo[256 * 128];

// ---------------- helpers ----------------
__device__ __forceinline__ uint32_t smem_u32(const void* p) {
    uint32_t a;
    asm("{ .reg .u64 t; cvta.to.shared.u64 t, %1; cvt.u32.u64 %0, t; }" : "=r"(a) : "l"(p));
    return a;
}
__device__ __forceinline__ void ldsm_x4(uint32_t* r, uint32_t addr) {
    asm volatile("ldmatrix.sync.aligned.m8n8.x4.shared.b16 {%0,%1,%2,%3}, [%4];"
        : "=r"(r[0]), "=r"(r[1]), "=r"(r[2]), "=r"(r[3]) : "r"(addr));
}
__device__ __forceinline__ void mma_bf16(float* d, const uint32_t* a, const uint32_t* b) {
    asm volatile("mma.sync.aligned.m16n8k16.row.col.f32.bf16.bf16.f32 "
        "{%0,%1,%2,%3}, {%4,%5,%6,%7}, {%8,%9}, {%0,%1,%2,%3};"
        : "+f"(d[0]), "+f"(d[1]), "+f"(d[2]), "+f"(d[3])
        : "r"(a[0]), "r"(a[1]), "r"(a[2]), "r"(a[3]), "r"(b[0]), "r"(b[1]));
}
__device__ __forceinline__ uint32_t pack_bf2(__nv_bfloat16 lo, __nv_bfloat16 hi) {
    return (uint32_t)__bfloat16_as_ushort(hi) << 16 | __bfloat16_as_ushort(lo);
}

// ---------------------------------------------------------------------------
__global__ void zero_all() {
    size_t stride = (size_t)gridDim.x * blockDim.x;
    size_t tid = (size_t)blockIdx.x * blockDim.x + threadIdx.x;
    float4* pa = reinterpret_cast<float4*>(g_A);
    const size_t na = (size_t)N_NODES * F_NODE / 4;
    for (size_t i = tid; i < na; i += stride) pa[i] = make_float4(0.f, 0.f, 0.f, 0.f);
    float4* pb = reinterpret_cast<float4*>(g_B);
    const size_t nb = (size_t)N_NODES * F_HEDGE / 4;
    for (size_t i = tid; i < nb; i += stride) pb[i] = make_float4(0.f, 0.f, 0.f, 0.f);
    for (size_t i = tid; i < N_NODES; i += stride) { g_c[i] = 0.f; g_c2[i] = 0.f; }
}

// ---------------------------------------------------------------------------
// Segmented scatter (unchanged — passing since R1)
// ---------------------------------------------------------------------------
template <int F, int EPG>
__global__ __launch_bounds__(256) void scatter_seg(
    const float* __restrict__ feat, const int* __restrict__ send,
    const int* __restrict__ recv, const float* __restrict__ conv, int nE)
{
    constexpr int G  = F / 4;
    constexpr int NG = 256 / G;
    constexpr int SPAN = NG * EPG;

    __shared__ int   sh_s[SPAN];
    __shared__ int   sh_r[SPAN];
    __shared__ float sh_c[SPAN];

    float* outp = (F == F_NODE) ? g_A : g_B;
    float* csum = (F == F_NODE) ? g_c : g_c2;

    const int tid = threadIdx.x;
    const int blockBase = blockIdx.x * SPAN;
    int cnt = nE - blockBase;
    if (cnt > SPAN) cnt = SPAN;

    for (int i = tid; i < cnt; i += 256) {
        sh_s[i] = send[blockBase + i];
        sh_r[i] = recv[blockBase + i];
        sh_c[i] = conv[blockBase + i];
    }
    __syncthreads();

    const int g    = tid / G;
    const int lane = tid % G;
    const int e0 = g * EPG;
    int e1 = e0 + EPG;
    if (e1 > cnt) e1 = cnt;
    if (e0 >= e1) return;

    float4 acc = make_float4(0.f, 0.f, 0.f, 0.f);
    float  accc = 0.f;
    int cur = sh_r[e0];
    float4 v = *reinterpret_cast<const float4*>(feat + (size_t)sh_s[e0] * F + lane * 4);

    for (int e = e0; e < e1; ++e) {
        float4 vcur = v;
        if (e + 1 < e1)
            v = *reinterpret_cast<const float4*>(feat + (size_t)sh_s[e + 1] * F + lane * 4);
        int r = sh_r[e];
        if (r != cur) {
            float* o = outp + (size_t)cur * F + lane * 4;
            atomicAdd(o + 0, acc.x); atomicAdd(o + 1, acc.y);
            atomicAdd(o + 2, acc.z); atomicAdd(o + 3, acc.w);
            acc = make_float4(0.f, 0.f, 0.f, 0.f);
            if (lane == 0) { atomicAdd(csum + cur, accc); accc = 0.f; }
            cur = r;
        }
        float cv = sh_c[e];
        acc.x += cv * vcur.x; acc.y += cv * vcur.y;
        acc.z += cv * vcur.z; acc.w += cv * vcur.w;
        if (lane == 0) accc += cv;
    }
    float* o = outp + (size_t)cur * F + lane * 4;
    atomicAdd(o + 0, acc.x); atomicAdd(o + 1, acc.y);
    atomicAdd(o + 2, acc.z); atomicAdd(o + 3, acc.w);
    if (lane == 0) atomicAdd(csum + cur, accc);
}

// ---------------------------------------------------------------------------
// Convert W -> transposed bf16 hi/lo ([n][k] layout)
// ---------------------------------------------------------------------------
__global__ void convert_W(const float* __restrict__ Wm, const float* __restrict__ Ws) {
    int t = blockIdx.x * 256 + threadIdx.x;
    if (t < 256 * 256) {
        int k = t >> 8, n = t & 255;
        float v = Wm[t];
        __nv_bfloat16 h = __float2bfloat16(v);
        g_Wm_hi[n * 256 + k] = h;
        g_Wm_lo[n * 256 + k] = __float2bfloat16(v - __bfloat162float(h));
    }
    if (t < 128 * 256) {
        int k = t >> 8, n = t & 255;
        float v = Ws[t];
        __nv_bfloat16 h = __float2bfloat16(v);
        g_Ws_hi[n * 128 + k] = h;
        g_Ws_lo[n * 128 + k] = __float2bfloat16(v - __bfloat162float(h));
    }
}

// ---------------------------------------------------------------------------
// Warp-tiled mma.sync bf16 GEMM, hi/lo split done on-the-fly from fp32 A.
//   BRANCH 0: g_M = g_A[128xK=256] @ Wm^T + c (x) b       (write g_M)
//   BRANCH 1: out = (g_B[128xK=128] @ Ws^T + c2 (x) b) * g_M
// CTA 128x128 (grid.y=2), 8 warps (4x2), warp tile 32x64, KC=32/stage.
// 3-pass inner loop reuses B-frag registers to stay under the 128-reg cap.
// ---------------------------------------------------------------------------
template <int BRANCH>
__global__ __launch_bounds__(256, 2) void gemm_mma(
    const float* __restrict__ bias, float* __restrict__ outp)
{
    constexpr int KTOT = BRANCH ? F_HEDGE : F_NODE;
    const float* __restrict__ srcA = BRANCH ? g_B : g_A;
    const __nv_bfloat16* __restrict__ Whi = BRANCH ? g_Ws_hi : g_Wm_hi;
    const __nv_bfloat16* __restrict__ Wlo = BRANCH ? g_Ws_lo : g_Wm_lo;
    const float* __restrict__ csum = BRANCH ? g_c2 : g_c;

    __shared__ __nv_bfloat16 sAh[128][40];
    __shared__ __nv_bfloat16 sAl[128][40];
    __shared__ __nv_bfloat16 sBh[128][40];
    __shared__ __nv_bfloat16 sBl[128][40];

    const int tid  = threadIdx.x;
    const int lane = tid & 31;
    const int wid  = tid >> 5;
    const int wm   = wid & 3;          // warp row block (32 rows)
    const int wn   = wid >> 2;         // warp col block (64 cols)
    const int r0   = blockIdx.x * 128;
    const int n0   = blockIdx.y * 128;

    float acc[2][8][4];
#pragma unroll
    for (int i = 0; i < 2; ++i)
#pragma unroll
        for (int j = 0; j < 8; ++j)
#pragma unroll
            for (int q = 0; q < 4; ++q) acc[i][j][q] = 0.f;

    // ldmatrix source addresses (fixed per thread)
    const int a_row  = wm * 32 + (lane & 15);
    const int a_kof  = (lane >> 4) * 8;
    const int b_nrow = wn * 64 + (lane >> 4) * 8 + (lane & 7);
    const int b_kof  = ((lane >> 3) & 1) * 8;
    const uint32_t aAh0 = smem_u32(&sAh[a_row][a_kof]);
    const uint32_t aAl0 = smem_u32(&sAl[a_row][a_kof]);
    const uint32_t aBh0 = smem_u32(&sBh[b_nrow][b_kof]);
    const uint32_t aBl0 = smem_u32(&sBl[b_nrow][b_kof]);

    for (int kc = 0; kc < KTOT / 32; ++kc) {
        // ---- A fill: 128 rows x 32 k fp32 -> hi/lo bf16 ----
#pragma unroll
        for (int p = 0; p < 4; ++p) {
            int idx = tid + p * 256;       // 0..1023
            int row = idx >> 3, j = idx & 7;
            int rr = r0 + row;
            float4 v = make_float4(0.f, 0.f, 0.f, 0.f);
            if (rr < N_NODES)
                v = *reinterpret_cast<const float4*>(srcA + (size_t)rr * KTOT + kc * 32 + j * 4);
            __nv_bfloat16 hx = __float2bfloat16(v.x), hy = __float2bfloat16(v.y);
            __nv_bfloat16 hz = __float2bfloat16(v.z), hw = __float2bfloat16(v.w);
            *reinterpret_cast<uint2*>(&sAh[row][j * 4]) =
                make_uint2(pack_bf2(hx, hy), pack_bf2(hz, hw));
            *reinterpret_cast<uint2*>(&sAl[row][j * 4]) = make_uint2(
                pack_bf2(__float2bfloat16(v.x - __bfloat162float(hx)),
                         __float2bfloat16(v.y - __bfloat162float(hy))),
                pack_bf2(__float2bfloat16(v.z - __bfloat162float(hz)),
                         __float2bfloat16(v.w - __bfloat162float(hw))));
        }
        // ---- B fill: 128 n-rows x 32 k, pre-split bf16 ----
#pragma unroll
        for (int p = 0; p < 2; ++p) {
            int idx = tid + p * 256;       // 0..511
            int row = idx >> 2, j = idx & 3;
            size_t woff = (size_t)(n0 + row) * KTOT + kc * 32 + j * 8;
            *reinterpret_cast<uint4*>(&sBh[row][j * 8]) =
                *reinterpret_cast<const uint4*>(Whi + woff);
            *reinterpret_cast<uint4*>(&sBl[row][j * 8]) =
                *reinterpret_cast<const uint4*>(Wlo + woff);
        }
        __syncthreads();

#pragma unroll
        for (int kk = 0; kk < 2; ++kk) {
            const uint32_t ko = kk * 32;   // 16 bf16 = 32 bytes
            uint32_t a[2][4], b[8][2];
            // pass 1+2: A_hi x (B_hi, B_lo)
#pragma unroll
            for (int mt = 0; mt < 2; ++mt) ldsm_x4(a[mt], aAh0 + mt * (16 * 80) + ko);
#pragma unroll
            for (int j2 = 0; j2 < 4; ++j2) {
                uint32_t m[4];
                ldsm_x4(m, aBh0 + j2 * (16 * 80) + ko);
                b[j2 * 2][0] = m[0]; b[j2 * 2][1] = m[1];
                b[j2 * 2 + 1][0] = m[2]; b[j2 * 2 + 1][1] = m[3];
            }
#pragma unroll
            for (int mt = 0; mt < 2; ++mt)
#pragma unroll
                for (int nf = 0; nf < 8; ++nf) mma_bf16(acc[mt][nf], a[mt], b[nf]);
#pragma unroll
            for (int j2 = 0; j2 < 4; ++j2) {
                uint32_t m[4];
                ldsm_x4(m, aBl0 + j2 * (16 * 80) + ko);
                b[j2 * 2][0] = m[0]; b[j2 * 2][1] = m[1];
                b[j2 * 2 + 1][0] = m[2]; b[j2 * 2 + 1][1] = m[3];
            }
#pragma unroll
            for (int mt = 0; mt < 2; ++mt)
#pragma unroll
                for (int nf = 0; nf < 8; ++nf) mma_bf16(acc[mt][nf], a[mt], b[nf]);
            // pass 3: A_lo x B_hi
#pragma unroll
            for (int mt = 0; mt < 2; ++mt) ldsm_x4(a[mt], aAl0 + mt * (16 * 80) + ko);
#pragma unroll
            for (int j2 = 0; j2 < 4; ++j2) {
                uint32_t m[4];
                ldsm_x4(m, aBh0 + j2 * (16 * 80) + ko);
                b[j2 * 2][0] = m[0]; b[j2 * 2][1] = m[1];
                b[j2 * 2 + 1][0] = m[2]; b[j2 * 2 + 1][1] = m[3];
            }
#pragma unroll
            for (int mt = 0; mt < 2; ++mt)
#pragma unroll
                for (int nf = 0; nf < 8; ++nf) mma_bf16(acc[mt][nf], a[mt], b[nf]);
        }
        __syncthreads();
    }

    // ---- epilogue ----
#pragma unroll
    for (int mt = 0; mt < 2; ++mt) {
        int rlo = r0 + wm * 32 + mt * 16 + (lane >> 2);
        int rhi = rlo + 8;
        float clo = (rlo < N_NODES) ? csum[rlo] : 0.f;
        float chi = (rhi < N_NODES) ? csum[rhi] : 0.f;
#pragma unroll
        for (int nf = 0; nf < 8; ++nf) {
            int n = n0 + wn * 64 + nf * 8 + (lane & 3) * 2;
            float b0 = __ldg(bias + n), b1 = __ldg(bias + n + 1);
            float v0 = acc[mt][nf][0] + clo * b0;
            float v1 = acc[mt][nf][1] + clo * b1;
            float v2 = acc[mt][nf][2] + chi * b0;
            float v3 = acc[mt][nf][3] + chi * b1;
            if (BRANCH) {
                if (rlo < N_NODES) {
                    float2 m = *reinterpret_cast<const float2*>(g_M + (size_t)rlo * 256 + n);
                    *reinterpret_cast<float2*>(outp + (size_t)rlo * 256 + n) =
                        make_float2(v0 * m.x, v1 * m.y);
                }
                if (rhi < N_NODES) {
                    float2 m = *reinterpret_cast<const float2*>(g_M + (size_t)rhi * 256 + n);
                    *reinterpret_cast<float2*>(outp + (size_t)rhi * 256 + n) =
                        make_float2(v2 * m.x, v3 * m.y);
                }
            } else {
                if (rlo < N_NODES)
                    *reinterpret_cast<float2*>(g_M + (size_t)rlo * 256 + n) = make_float2(v0, v1);
                if (rhi < N_NODES)
                    *reinterpret_cast<float2*>(g_M + (size_t)rhi * 256 + n) = make_float2(v2, v3);
            }
        }
    }
}

// ---------------------------------------------------------------------------
extern "C" void kernel_launch(void* const* d_in, const int* in_sizes, int n_in,
                              void* d_out, int out_size)
{
    const float* node_features  = (const float*)d_in[0];
    const float* hedge_features = (const float*)d_in[1];
    const int*   node_senders   = (const int*)d_in[2];
    const int*   node_receivers = (const int*)d_in[3];
    const float* node_conv      = (const float*)d_in[4];
    const int*   h_senders      = (const int*)d_in[5];
    const int*   h_receivers    = (const int*)d_in[6];
    const float* h_conv         = (const float*)d_in[7];
    const float* W_msg          = (const float*)d_in[8];
    const float* b_msg          = (const float*)d_in[9];
    const float* W_scale        = (const float*)d_in[10];
    const float* b_scale        = (const float*)d_in[11];
    float* out = (float*)d_out;

    const int nE  = in_sizes[2];
    const int nE2 = in_sizes[5];

    zero_all<<<1024, 256>>>();
    scatter_seg<256, 128><<<(nE + 511) / 512, 256>>>(
        node_features, node_senders, node_receivers, node_conv, nE);
    scatter_seg<128, 128><<<(nE2 + 1023) / 1024, 256>>>(
        hedge_features, h_senders, h_receivers, h_conv, nE2);
    convert_W<<<256, 256>>>(W_msg, W_scale);

    dim3 grid((N_NODES + 127) / 128, 2);
    gemm_mma<0><<<grid, 256>>>(b_msg, nullptr);   // msg branch -> g_M
    gemm_mma<1><<<grid, 256>>>(b_scale, out);     // scale branch * g_M -> out
}

// round 10
// speedup vs baseline: 1.9594x; 1.1558x over previous
#include <cuda_runtime.h>
#include <cuda_bf16.h>
#include <cstdint>

#define N_NODES 50000
#define F_NODE  256
#define F_HEDGE 128

// ---------------- scratch (device globals; allocation-free) ----------------
__device__ float g_A[(size_t)N_NODES * F_NODE];   // segsum(conv * x[s])
__device__ float g_B[(size_t)N_NODES * F_HEDGE];  // segsum(conv2 * h[s2])
__device__ float g_c[N_NODES];                    // segsum(conv)
__device__ float g_c2[N_NODES];                   // segsum(conv2)
// W transposed to [n][k], split hi/lo bf16
__device__ __nv_bfloat16 g_Wm_hi[256 * 256];
__device__ __nv_bfloat16 g_Wm_lo[256 * 256];
__device__ __nv_bfloat16 g_Ws_hi[256 * 128];
__device__ __nv_bfloat16 g_Ws_lo[256 * 128];

// ---------------- helpers ----------------
__device__ __forceinline__ uint32_t smem_u32(const void* p) {
    uint32_t a;
    asm("{ .reg .u64 t; cvta.to.shared.u64 t, %1; cvt.u32.u64 %0, t; }" : "=r"(a) : "l"(p));
    return a;
}
__device__ __forceinline__ void ldsm_x4(uint32_t* r, uint32_t addr) {
    asm volatile("ldmatrix.sync.aligned.m8n8.x4.shared.b16 {%0,%1,%2,%3}, [%4];"
        : "=r"(r[0]), "=r"(r[1]), "=r"(r[2]), "=r"(r[3]) : "r"(addr));
}
__device__ __forceinline__ void mma_bf16(float* d, const uint32_t* a, const uint32_t* b) {
    asm volatile("mma.sync.aligned.m16n8k16.row.col.f32.bf16.bf16.f32 "
        "{%0,%1,%2,%3}, {%4,%5,%6,%7}, {%8,%9}, {%0,%1,%2,%3};"
        : "+f"(d[0]), "+f"(d[1]), "+f"(d[2]), "+f"(d[3])
        : "r"(a[0]), "r"(a[1]), "r"(a[2]), "r"(a[3]), "r"(b[0]), "r"(b[1]));
}
__device__ __forceinline__ uint32_t pack_bf2(__nv_bfloat16 lo, __nv_bfloat16 hi) {
    return (uint32_t)__bfloat16_as_ushort(hi) << 16 | __bfloat16_as_ushort(lo);
}
__device__ __forceinline__ void cp_async16(uint32_t s, const void* g) {
    asm volatile("cp.async.cg.shared.global [%0], [%1], 16;"
        :: "r"(s), "l"((unsigned long long)__cvta_generic_to_global(g)) : "memory");
}

// SMEM layout (dynamic): Ah 0, Al 10240, Bh 20480, Bl 30720, stash 40960
#define OFF_AH 0u
#define OFF_AL 10240u
#define OFF_BH 20480u
#define OFF_BL 30720u
#define OFF_ST 40960u
#define SMEM_BYTES (40960 + 65536)

// ---------------------------------------------------------------------------
__global__ void zero_all() {
    size_t stride = (size_t)gridDim.x * blockDim.x;
    size_t tid = (size_t)blockIdx.x * blockDim.x + threadIdx.x;
    float4* pa = reinterpret_cast<float4*>(g_A);
    const size_t na = (size_t)N_NODES * F_NODE / 4;
    for (size_t i = tid; i < na; i += stride) pa[i] = make_float4(0.f, 0.f, 0.f, 0.f);
    float4* pb = reinterpret_cast<float4*>(g_B);
    const size_t nb = (size_t)N_NODES * F_HEDGE / 4;
    for (size_t i = tid; i < nb; i += stride) pb[i] = make_float4(0.f, 0.f, 0.f, 0.f);
    for (size_t i = tid; i < N_NODES; i += stride) { g_c[i] = 0.f; g_c2[i] = 0.f; }
}

// ---------------------------------------------------------------------------
// Segmented scatter (unchanged — passing since R1)
// ---------------------------------------------------------------------------
template <int F, int EPG>
__global__ __launch_bounds__(256) void scatter_seg(
    const float* __restrict__ feat, const int* __restrict__ send,
    const int* __restrict__ recv, const float* __restrict__ conv, int nE)
{
    constexpr int G  = F / 4;
    constexpr int NG = 256 / G;
    constexpr int SPAN = NG * EPG;

    __shared__ int   sh_s[SPAN];
    __shared__ int   sh_r[SPAN];
    __shared__ float sh_c[SPAN];

    float* outp = (F == F_NODE) ? g_A : g_B;
    float* csum = (F == F_NODE) ? g_c : g_c2;

    const int tid = threadIdx.x;
    const int blockBase = blockIdx.x * SPAN;
    int cnt = nE - blockBase;
    if (cnt > SPAN) cnt = SPAN;

    for (int i = tid; i < cnt; i += 256) {
        sh_s[i] = send[blockBase + i];
        sh_r[i] = recv[blockBase + i];
        sh_c[i] = conv[blockBase + i];
    }
    __syncthreads();

    const int g    = tid / G;
    const int lane = tid % G;
    const int e0 = g * EPG;
    int e1 = e0 + EPG;
    if (e1 > cnt) e1 = cnt;
    if (e0 >= e1) return;

    float4 acc = make_float4(0.f, 0.f, 0.f, 0.f);
    float  accc = 0.f;
    int cur = sh_r[e0];
    float4 v = *reinterpret_cast<const float4*>(feat + (size_t)sh_s[e0] * F + lane * 4);

    for (int e = e0; e < e1; ++e) {
        float4 vcur = v;
        if (e + 1 < e1)
            v = *reinterpret_cast<const float4*>(feat + (size_t)sh_s[e + 1] * F + lane * 4);
        int r = sh_r[e];
        if (r != cur) {
            float* o = outp + (size_t)cur * F + lane * 4;
            atomicAdd(o + 0, acc.x); atomicAdd(o + 1, acc.y);
            atomicAdd(o + 2, acc.z); atomicAdd(o + 3, acc.w);
            acc = make_float4(0.f, 0.f, 0.f, 0.f);
            if (lane == 0) { atomicAdd(csum + cur, accc); accc = 0.f; }
            cur = r;
        }
        float cv = sh_c[e];
        acc.x += cv * vcur.x; acc.y += cv * vcur.y;
        acc.z += cv * vcur.z; acc.w += cv * vcur.w;
        if (lane == 0) accc += cv;
    }
    float* o = outp + (size_t)cur * F + lane * 4;
    atomicAdd(o + 0, acc.x); atomicAdd(o + 1, acc.y);
    atomicAdd(o + 2, acc.z); atomicAdd(o + 3, acc.w);
    if (lane == 0) atomicAdd(csum + cur, accc);
}

// ---------------------------------------------------------------------------
// Convert W -> transposed bf16 hi/lo ([n][k] layout)
// ---------------------------------------------------------------------------
__global__ void convert_W(const float* __restrict__ Wm, const float* __restrict__ Ws) {
    int t = blockIdx.x * 256 + threadIdx.x;
    if (t < 256 * 256) {
        int k = t >> 8, n = t & 255;
        float v = Wm[t];
        __nv_bfloat16 h = __float2bfloat16(v);
        g_Wm_hi[n * 256 + k] = h;
        g_Wm_lo[n * 256 + k] = __float2bfloat16(v - __bfloat162float(h));
    }
    if (t < 128 * 256) {
        int k = t >> 8, n = t & 255;
        float v = Ws[t];
        __nv_bfloat16 h = __float2bfloat16(v);
        g_Ws_hi[n * 128 + k] = h;
        g_Ws_lo[n * 128 + k] = __float2bfloat16(v - __bfloat162float(h));
    }
}

// ---------------------------------------------------------------------------
// One GEMM pass over K: acc += split_bf16(srcA[128 x KTOT]) @ W^T
// cp.async B tiles overlap with A fp32->hi/lo conversion; 12-ldmatrix inner.
// ---------------------------------------------------------------------------
template <int KTOT>
__device__ __forceinline__ void gemm_tiles(
    const float* __restrict__ srcA,
    const __nv_bfloat16* __restrict__ Whi, const __nv_bfloat16* __restrict__ Wlo,
    char* sm, uint32_t smb, int r0, int n0, int tid,
    uint32_t aAh0, uint32_t aAl0, uint32_t aBh0, uint32_t aBl0,
    float acc[2][8][4])
{
    for (int kc = 0; kc < KTOT / 32; ++kc) {
        // ---- B fill via cp.async (hi + lo, 512 x 16B total) ----
#pragma unroll
        for (int p = 0; p < 4; ++p) {
            int c = tid + (p & 1) * 256;       // 0..511
            int row = c >> 2, j = c & 3;
            const __nv_bfloat16* gp = ((p >> 1) ? Wlo : Whi)
                + (size_t)(n0 + row) * KTOT + kc * 32 + j * 8;
            uint32_t sp = smb + ((p >> 1) ? OFF_BL : OFF_BH) + row * 80 + j * 16;
            cp_async16(sp, gp);
        }
        asm volatile("cp.async.commit_group;" ::: "memory");

        // ---- A fill: 128 rows x 32 k fp32 -> hi/lo bf16 (overlaps cp.async) ----
#pragma unroll
        for (int p = 0; p < 4; ++p) {
            int idx = tid + p * 256;           // 0..1023
            int row = idx >> 3, j = idx & 7;
            int rr = r0 + row;
            float4 v = make_float4(0.f, 0.f, 0.f, 0.f);
            if (rr < N_NODES)
                v = *reinterpret_cast<const float4*>(srcA + (size_t)rr * KTOT + kc * 32 + j * 4);
            __nv_bfloat16 hx = __float2bfloat16(v.x), hy = __float2bfloat16(v.y);
            __nv_bfloat16 hz = __float2bfloat16(v.z), hw = __float2bfloat16(v.w);
            *reinterpret_cast<uint2*>(sm + OFF_AH + row * 80 + j * 8) =
                make_uint2(pack_bf2(hx, hy), pack_bf2(hz, hw));
            *reinterpret_cast<uint2*>(sm + OFF_AL + row * 80 + j * 8) = make_uint2(
                pack_bf2(__float2bfloat16(v.x - __bfloat162float(hx)),
                         __float2bfloat16(v.y - __bfloat162float(hy))),
                pack_bf2(__float2bfloat16(v.z - __bfloat162float(hz)),
                         __float2bfloat16(v.w - __bfloat162float(hw))));
        }
        asm volatile("cp.async.wait_group 0;" ::: "memory");
        __syncthreads();

        // ---- MMA: per k16, hold Ahi+Alo, Bhi once for 2 passes, then Blo ----
#pragma unroll
        for (int kk = 0; kk < 2; ++kk) {
            const uint32_t ko = kk * 32;       // 16 bf16 = 32 bytes
            uint32_t ah[2][4], al[2][4], b[8][2];
#pragma unroll
            for (int mt = 0; mt < 2; ++mt) {
                ldsm_x4(ah[mt], aAh0 + mt * (16 * 80) + ko);
                ldsm_x4(al[mt], aAl0 + mt * (16 * 80) + ko);
            }
#pragma unroll
            for (int j2 = 0; j2 < 4; ++j2) {
                uint32_t m[4];
                ldsm_x4(m, aBh0 + j2 * (16 * 80) + ko);
                b[j2 * 2][0] = m[0]; b[j2 * 2][1] = m[1];
                b[j2 * 2 + 1][0] = m[2]; b[j2 * 2 + 1][1] = m[3];
            }
#pragma unroll
            for (int mt = 0; mt < 2; ++mt)
#pragma unroll
                for (int nf = 0; nf < 8; ++nf) {
                    mma_bf16(acc[mt][nf], ah[mt], b[nf]);
                    mma_bf16(acc[mt][nf], al[mt], b[nf]);
                }
#pragma unroll
            for (int j2 = 0; j2 < 4; ++j2) {
                uint32_t m[4];
                ldsm_x4(m, aBl0 + j2 * (16 * 80) + ko);
                b[j2 * 2][0] = m[0]; b[j2 * 2][1] = m[1];
                b[j2 * 2 + 1][0] = m[2]; b[j2 * 2 + 1][1] = m[3];
            }
#pragma unroll
            for (int mt = 0; mt < 2; ++mt)
#pragma unroll
                for (int nf = 0; nf < 8; ++nf)
                    mma_bf16(acc[mt][nf], ah[mt], b[nf]);
        }
        __syncthreads();
    }
}

// ---------------------------------------------------------------------------
// Fused dual-GEMM: branch0 (g_A @ Wm + c (x) bm) -> smem stash,
// branch1 (g_B @ Ws + c2 (x) bs), combine, store out. No g_M round trip.
// ---------------------------------------------------------------------------
__global__ __launch_bounds__(256, 2) void gemm_fused(
    const float* __restrict__ bm, const float* __restrict__ bs,
    float* __restrict__ out)
{
    extern __shared__ char sm[];
    const uint32_t smb = smem_u32(sm);
    float* stash = reinterpret_cast<float*>(sm + OFF_ST);

    const int tid  = threadIdx.x;
    const int lane = tid & 31;
    const int wid  = tid >> 5;
    const int wm   = wid & 3;
    const int wn   = wid >> 2;
    const int r0   = blockIdx.x * 128;
    const int n0   = blockIdx.y * 128;

    const int a_row  = wm * 32 + (lane & 15);
    const int a_kof  = (lane >> 4) * 8;
    const int b_nrow = wn * 64 + (lane >> 4) * 8 + (lane & 7);
    const int b_kof  = ((lane >> 3) & 1) * 8;
    const uint32_t aAh0 = smb + OFF_AH + a_row * 80 + a_kof * 2;
    const uint32_t aAl0 = smb + OFF_AL + a_row * 80 + a_kof * 2;
    const uint32_t aBh0 = smb + OFF_BH + b_nrow * 80 + b_kof * 2;
    const uint32_t aBl0 = smb + OFF_BL + b_nrow * 80 + b_kof * 2;

    float acc[2][8][4];
#pragma unroll
    for (int i = 0; i < 2; ++i)
#pragma unroll
        for (int j = 0; j < 8; ++j)
#pragma unroll
            for (int q = 0; q < 4; ++q) acc[i][j][q] = 0.f;

    // ---- branch 0: msg GEMM over g_A / Wm ----
    gemm_tiles<F_NODE>(g_A, g_Wm_hi, g_Wm_lo, sm, smb, r0, n0, tid,
                       aAh0, aAl0, aBh0, aBl0, acc);

    // stash (bias applied); per-thread interleaved -> conflict-free
#pragma unroll
    for (int mt = 0; mt < 2; ++mt) {
        int rlo = r0 + wm * 32 + mt * 16 + (lane >> 2);
        int rhi = rlo + 8;
        float clo = (rlo < N_NODES) ? g_c[rlo] : 0.f;
        float chi = (rhi < N_NODES) ? g_c[rhi] : 0.f;
#pragma unroll
        for (int nf = 0; nf < 8; ++nf) {
            int n = n0 + wn * 64 + nf * 8 + (lane & 3) * 2;
            float b0 = __ldg(bm + n), b1 = __ldg(bm + n + 1);
            int j = mt * 32 + nf * 4;
            stash[(j + 0) * 256 + tid] = acc[mt][nf][0] + clo * b0;
            stash[(j + 1) * 256 + tid] = acc[mt][nf][1] + clo * b1;
            stash[(j + 2) * 256 + tid] = acc[mt][nf][2] + chi * b0;
            stash[(j + 3) * 256 + tid] = acc[mt][nf][3] + chi * b1;
        }
    }

#pragma unroll
    for (int i = 0; i < 2; ++i)
#pragma unroll
        for (int j = 0; j < 8; ++j)
#pragma unroll
            for (int q = 0; q < 4; ++q) acc[i][j][q] = 0.f;

    // ---- branch 1: scale GEMM over g_B / Ws ----
    gemm_tiles<F_HEDGE>(g_B, g_Ws_hi, g_Ws_lo, sm, smb, r0, n0, tid,
                        aAh0, aAl0, aBh0, aBl0, acc);

    // ---- combine epilogue ----
#pragma unroll
    for (int mt = 0; mt < 2; ++mt) {
        int rlo = r0 + wm * 32 + mt * 16 + (lane >> 2);
        int rhi = rlo + 8;
        float clo = (rlo < N_NODES) ? g_c2[rlo] : 0.f;
        float chi = (rhi < N_NODES) ? g_c2[rhi] : 0.f;
#pragma unroll
        for (int nf = 0; nf < 8; ++nf) {
            int n = n0 + wn * 64 + nf * 8 + (lane & 3) * 2;
            float b0 = __ldg(bs + n), b1 = __ldg(bs + n + 1);
            int j = mt * 32 + nf * 4;
            float m0 = stash[(j + 0) * 256 + tid];
            float m1 = stash[(j + 1) * 256 + tid];
            float m2 = stash[(j + 2) * 256 + tid];
            float m3 = stash[(j + 3) * 256 + tid];
            if (rlo < N_NODES)
                *reinterpret_cast<float2*>(out + (size_t)rlo * 256 + n) =
                    make_float2((acc[mt][nf][0] + clo * b0) * m0,
                                (acc[mt][nf][1] + clo * b1) * m1);
            if (rhi < N_NODES)
                *reinterpret_cast<float2*>(out + (size_t)rhi * 256 + n) =
                    make_float2((acc[mt][nf][2] + chi * b0) * m2,
                                (acc[mt][nf][3] + chi * b1) * m3);
        }
    }
}

// ---------------------------------------------------------------------------
extern "C" void kernel_launch(void* const* d_in, const int* in_sizes, int n_in,
                              void* d_out, int out_size)
{
    const float* node_features  = (const float*)d_in[0];
    const float* hedge_features = (const float*)d_in[1];
    const int*   node_senders   = (const int*)d_in[2];
    const int*   node_receivers = (const int*)d_in[3];
    const float* node_conv      = (const float*)d_in[4];
    const int*   h_senders      = (const int*)d_in[5];
    const int*   h_receivers    = (const int*)d_in[6];
    const float* h_conv         = (const float*)d_in[7];
    const float* W_msg          = (const float*)d_in[8];
    const float* b_msg          = (const float*)d_in[9];
    const float* W_scale        = (const float*)d_in[10];
    const float* b_scale        = (const float*)d_in[11];
    float* out = (float*)d_out;

    const int nE  = in_sizes[2];
    const int nE2 = in_sizes[5];

    cudaFuncSetAttribute(gemm_fused, cudaFuncAttributeMaxDynamicSharedMemorySize, SMEM_BYTES);

    zero_all<<<1024, 256>>>();
    scatter_seg<256, 128><<<(nE + 511) / 512, 256>>>(
        node_features, node_senders, node_receivers, node_conv, nE);
    scatter_seg<128, 128><<<(nE2 + 1023) / 1024, 256>>>(
        hedge_features, h_senders, h_receivers, h_conv, nE2);
    convert_W<<<256, 256>>>(W_msg, W_scale);

    dim3 grid((N_NODES + 127) / 128, 2);
    gemm_fused<<<grid, 256, SMEM_BYTES>>>(b_msg, b_scale, out);
}

// round 11
// speedup vs baseline: 1.9886x; 1.0149x over previous
#include <cuda_runtime.h>
#include <cuda_bf16.h>
#include <cstdint>

#define N_NODES 50000
#define F_NODE  256
#define F_HEDGE 128

// ---------------- scratch (device globals; allocation-free) ----------------
__device__ float g_A[(size_t)N_NODES * F_NODE];   // segsum(conv * x[s])
__device__ float g_B[(size_t)N_NODES * F_HEDGE];  // segsum(conv2 * h[s2])
__device__ float g_c[N_NODES];                    // segsum(conv)
__device__ float g_c2[N_NODES];                   // segsum(conv2)
// W transposed to [n][k], split hi/lo bf16
__device__ __nv_bfloat16 g_Wm_hi[256 * 256];
__device__ __nv_bfloat16 g_Wm_lo[256 * 256];
__device__ __nv_bfloat16 g_Ws_hi[256 * 128];
__device__ __nv_bfloat16 g_Ws_lo[256 * 128];

// ---------------- helpers ----------------
__device__ __forceinline__ uint32_t smem_u32(const void* p) {
    uint32_t a;
    asm("{ .reg .u64 t; cvta.to.shared.u64 t, %1; cvt.u32.u64 %0, t; }" : "=r"(a) : "l"(p));
    return a;
}
__device__ __forceinline__ void ldsm_x4(uint32_t* r, uint32_t addr) {
    asm volatile("ldmatrix.sync.aligned.m8n8.x4.shared.b16 {%0,%1,%2,%3}, [%4];"
        : "=r"(r[0]), "=r"(r[1]), "=r"(r[2]), "=r"(r[3]) : "r"(addr));
}
__device__ __forceinline__ void mma_bf16(float* d, const uint32_t* a, const uint32_t* b) {
    asm volatile("mma.sync.aligned.m16n8k16.row.col.f32.bf16.bf16.f32 "
        "{%0,%1,%2,%3}, {%4,%5,%6,%7}, {%8,%9}, {%0,%1,%2,%3};"
        : "+f"(d[0]), "+f"(d[1]), "+f"(d[2]), "+f"(d[3])
        : "r"(a[0]), "r"(a[1]), "r"(a[2]), "r"(a[3]), "r"(b[0]), "r"(b[1]));
}
__device__ __forceinline__ uint32_t pack_bf2(__nv_bfloat16 lo, __nv_bfloat16 hi) {
    return (uint32_t)__bfloat16_as_ushort(hi) << 16 | __bfloat16_as_ushort(lo);
}
__device__ __forceinline__ void cp_async16(uint32_t s, const void* g) {
    asm volatile("cp.async.cg.shared.global [%0], [%1], 16;"
        :: "r"(s), "l"((unsigned long long)__cvta_generic_to_global(g)) : "memory");
}

// SMEM layout (dynamic): Ah 0, Al 10240, Bh 20480, Bl 30720, stash 40960
#define OFF_AH 0u
#define OFF_AL 10240u
#define OFF_BH 20480u
#define OFF_BL 30720u
#define OFF_ST 40960u
#define SMEM_BYTES (40960 + 65536)

// ---------------------------------------------------------------------------
// prep: zero scratch (blocks >= 256) + convert W (blocks 0..255).
// W conversion is ALU work on a tiny footprint; zeroing is pure BW — they
// coexist in one launch, saving the separate convert_W kernel.
// ---------------------------------------------------------------------------
__global__ void prep(const float* __restrict__ Wm, const float* __restrict__ Ws) {
    if (blockIdx.x < 256) {
        int t = blockIdx.x * 256 + threadIdx.x;
        {
            int k = t >> 8, n = t & 255;
            float v = Wm[t];
            __nv_bfloat16 h = __float2bfloat16(v);
            g_Wm_hi[n * 256 + k] = h;
            g_Wm_lo[n * 256 + k] = __float2bfloat16(v - __bfloat162float(h));
        }
        if (t < 128 * 256) {
            int k = t >> 8, n = t & 255;
            float v = Ws[t];
            __nv_bfloat16 h = __float2bfloat16(v);
            g_Ws_hi[n * 128 + k] = h;
            g_Ws_lo[n * 128 + k] = __float2bfloat16(v - __bfloat162float(h));
        }
        return;
    }
    const size_t nz = (size_t)(gridDim.x - 256) * blockDim.x;
    size_t tid = (size_t)(blockIdx.x - 256) * blockDim.x + threadIdx.x;
    float4* pa = reinterpret_cast<float4*>(g_A);
    const size_t na = (size_t)N_NODES * F_NODE / 4;
    for (size_t i = tid; i < na; i += nz) pa[i] = make_float4(0.f, 0.f, 0.f, 0.f);
    float4* pb = reinterpret_cast<float4*>(g_B);
    const size_t nb = (size_t)N_NODES * F_HEDGE / 4;
    for (size_t i = tid; i < nb; i += nz) pb[i] = make_float4(0.f, 0.f, 0.f, 0.f);
    for (size_t i = tid; i < N_NODES; i += nz) { g_c[i] = 0.f; g_c2[i] = 0.f; }
}

// ---------------------------------------------------------------------------
// Segmented scatter (unchanged — passing since R1)
// ---------------------------------------------------------------------------
template <int F, int EPG>
__global__ __launch_bounds__(256) void scatter_seg(
    const float* __restrict__ feat, const int* __restrict__ send,
    const int* __restrict__ recv, const float* __restrict__ conv, int nE)
{
    constexpr int G  = F / 4;
    constexpr int NG = 256 / G;
    constexpr int SPAN = NG * EPG;

    __shared__ int   sh_s[SPAN];
    __shared__ int   sh_r[SPAN];
    __shared__ float sh_c[SPAN];

    float* outp = (F == F_NODE) ? g_A : g_B;
    float* csum = (F == F_NODE) ? g_c : g_c2;

    const int tid = threadIdx.x;
    const int blockBase = blockIdx.x * SPAN;
    int cnt = nE - blockBase;
    if (cnt > SPAN) cnt = SPAN;

    for (int i = tid; i < cnt; i += 256) {
        sh_s[i] = send[blockBase + i];
        sh_r[i] = recv[blockBase + i];
        sh_c[i] = conv[blockBase + i];
    }
    __syncthreads();

    const int g    = tid / G;
    const int lane = tid % G;
    const int e0 = g * EPG;
    int e1 = e0 + EPG;
    if (e1 > cnt) e1 = cnt;
    if (e0 >= e1) return;

    float4 acc = make_float4(0.f, 0.f, 0.f, 0.f);
    float  accc = 0.f;
    int cur = sh_r[e0];
    float4 v = *reinterpret_cast<const float4*>(feat + (size_t)sh_s[e0] * F + lane * 4);

    for (int e = e0; e < e1; ++e) {
        float4 vcur = v;
        if (e + 1 < e1)
            v = *reinterpret_cast<const float4*>(feat + (size_t)sh_s[e + 1] * F + lane * 4);
        int r = sh_r[e];
        if (r != cur) {
            float* o = outp + (size_t)cur * F + lane * 4;
            atomicAdd(o + 0, acc.x); atomicAdd(o + 1, acc.y);
            atomicAdd(o + 2, acc.z); atomicAdd(o + 3, acc.w);
            acc = make_float4(0.f, 0.f, 0.f, 0.f);
            if (lane == 0) { atomicAdd(csum + cur, accc); accc = 0.f; }
            cur = r;
        }
        float cv = sh_c[e];
        acc.x += cv * vcur.x; acc.y += cv * vcur.y;
        acc.z += cv * vcur.z; acc.w += cv * vcur.w;
        if (lane == 0) accc += cv;
    }
    float* o = outp + (size_t)cur * F + lane * 4;
    atomicAdd(o + 0, acc.x); atomicAdd(o + 1, acc.y);
    atomicAdd(o + 2, acc.z); atomicAdd(o + 3, acc.w);
    if (lane == 0) atomicAdd(csum + cur, accc);
}

// ---------------------------------------------------------------------------
// One GEMM pass over K: acc += split_bf16(srcA[128 x KTOT]) @ W^T
// cp.async B tiles; A-fill batches all 4 LDG.128s (MLP=4) before converts.
// ---------------------------------------------------------------------------
template <int KTOT>
__device__ __forceinline__ void gemm_tiles(
    const float* __restrict__ srcA,
    const __nv_bfloat16* __restrict__ Whi, const __nv_bfloat16* __restrict__ Wlo,
    char* sm, uint32_t smb, int r0, int n0, int tid,
    uint32_t aAh0, uint32_t aAl0, uint32_t aBh0, uint32_t aBl0,
    float acc[2][8][4])
{
    for (int kc = 0; kc < KTOT / 32; ++kc) {
        // ---- B fill via cp.async (hi + lo, 512 x 16B total) ----
#pragma unroll
        for (int p = 0; p < 4; ++p) {
            int c = tid + (p & 1) * 256;       // 0..511
            int row = c >> 2, j = c & 3;
            const __nv_bfloat16* gp = ((p >> 1) ? Wlo : Whi)
                + (size_t)(n0 + row) * KTOT + kc * 32 + j * 8;
            uint32_t sp = smb + ((p >> 1) ? OFF_BL : OFF_BH) + row * 80 + j * 16;
            cp_async16(sp, gp);
        }
        asm volatile("cp.async.commit_group;" ::: "memory");

        // ---- A fill: batch 4 LDG.128 first (MLP=4), then convert+store ----
        float4 v[4];
        int rows[4], js[4];
#pragma unroll
        for (int p = 0; p < 4; ++p) {
            int idx = tid + p * 256;           // 0..1023
            rows[p] = idx >> 3; js[p] = idx & 7;
            int rr = r0 + rows[p];
            v[p] = make_float4(0.f, 0.f, 0.f, 0.f);
            if (rr < N_NODES)
                v[p] = *reinterpret_cast<const float4*>(
                    srcA + (size_t)rr * KTOT + kc * 32 + js[p] * 4);
        }
#pragma unroll
        for (int p = 0; p < 4; ++p) {
            __nv_bfloat16 hx = __float2bfloat16(v[p].x), hy = __float2bfloat16(v[p].y);
            __nv_bfloat16 hz = __float2bfloat16(v[p].z), hw = __float2bfloat16(v[p].w);
            *reinterpret_cast<uint2*>(sm + OFF_AH + rows[p] * 80 + js[p] * 8) =
                make_uint2(pack_bf2(hx, hy), pack_bf2(hz, hw));
            *reinterpret_cast<uint2*>(sm + OFF_AL + rows[p] * 80 + js[p] * 8) = make_uint2(
                pack_bf2(__float2bfloat16(v[p].x - __bfloat162float(hx)),
                         __float2bfloat16(v[p].y - __bfloat162float(hy))),
                pack_bf2(__float2bfloat16(v[p].z - __bfloat162float(hz)),
                         __float2bfloat16(v[p].w - __bfloat162float(hw))));
        }
        asm volatile("cp.async.wait_group 0;" ::: "memory");
        __syncthreads();

        // ---- MMA: per k16, Bh serves both Ahi and Alo; then Bl x Ahi ----
#pragma unroll
        for (int kk = 0; kk < 2; ++kk) {
            const uint32_t ko = kk * 32;       // 16 bf16 = 32 bytes
            uint32_t ah[2][4], al[2][4], b[8][2];
#pragma unroll
            for (int mt = 0; mt < 2; ++mt) {
                ldsm_x4(ah[mt], aAh0 + mt * (16 * 80) + ko);
                ldsm_x4(al[mt], aAl0 + mt * (16 * 80) + ko);
            }
#pragma unroll
            for (int j2 = 0; j2 < 4; ++j2) {
                uint32_t m[4];
                ldsm_x4(m, aBh0 + j2 * (16 * 80) + ko);
                b[j2 * 2][0] = m[0]; b[j2 * 2][1] = m[1];
                b[j2 * 2 + 1][0] = m[2]; b[j2 * 2 + 1][1] = m[3];
            }
#pragma unroll
            for (int mt = 0; mt < 2; ++mt)
#pragma unroll
                for (int nf = 0; nf < 8; ++nf) {
                    mma_bf16(acc[mt][nf], ah[mt], b[nf]);
                    mma_bf16(acc[mt][nf], al[mt], b[nf]);
                }
#pragma unroll
            for (int j2 = 0; j2 < 4; ++j2) {
                uint32_t m[4];
                ldsm_x4(m, aBl0 + j2 * (16 * 80) + ko);
                b[j2 * 2][0] = m[0]; b[j2 * 2][1] = m[1];
                b[j2 * 2 + 1][0] = m[2]; b[j2 * 2 + 1][1] = m[3];
            }
#pragma unroll
            for (int mt = 0; mt < 2; ++mt)
#pragma unroll
                for (int nf = 0; nf < 8; ++nf)
                    mma_bf16(acc[mt][nf], ah[mt], b[nf]);
        }
        __syncthreads();
    }
}

// ---------------------------------------------------------------------------
// Fused dual-GEMM: branch0 (g_A @ Wm + c (x) bm) -> smem stash,
// branch1 (g_B @ Ws + c2 (x) bs), combine, store out.
// ---------------------------------------------------------------------------
__global__ __launch_bounds__(256, 2) void gemm_fused(
    const float* __restrict__ bm, const float* __restrict__ bs,
    float* __restrict__ out)
{
    extern __shared__ char sm[];
    const uint32_t smb = smem_u32(sm);
    float* stash = reinterpret_cast<float*>(sm + OFF_ST);

    const int tid  = threadIdx.x;
    const int lane = tid & 31;
    const int wid  = tid >> 5;
    const int wm   = wid & 3;
    const int wn   = wid >> 2;
    const int r0   = blockIdx.x * 128;
    const int n0   = blockIdx.y * 128;

    const int a_row  = wm * 32 + (lane & 15);
    const int a_kof  = (lane >> 4) * 8;
    const int b_nrow = wn * 64 + (lane >> 4) * 8 + (lane & 7);
    const int b_kof  = ((lane >> 3) & 1) * 8;
    const uint32_t aAh0 = smb + OFF_AH + a_row * 80 + a_kof * 2;
    const uint32_t aAl0 = smb + OFF_AL + a_row * 80 + a_kof * 2;
    const uint32_t aBh0 = smb + OFF_BH + b_nrow * 80 + b_kof * 2;
    const uint32_t aBl0 = smb + OFF_BL + b_nrow * 80 + b_kof * 2;

    float acc[2][8][4];
#pragma unroll
    for (int i = 0; i < 2; ++i)
#pragma unroll
        for (int j = 0; j < 8; ++j)
#pragma unroll
            for (int q = 0; q < 4; ++q) acc[i][j][q] = 0.f;

    // ---- branch 0: msg GEMM over g_A / Wm ----
    gemm_tiles<F_NODE>(g_A, g_Wm_hi, g_Wm_lo, sm, smb, r0, n0, tid,
                       aAh0, aAl0, aBh0, aBl0, acc);

    // stash (bias applied); per-thread interleaved -> conflict-free
#pragma unroll
    for (int mt = 0; mt < 2; ++mt) {
        int rlo = r0 + wm * 32 + mt * 16 + (lane >> 2);
        int rhi = rlo + 8;
        float clo = (rlo < N_NODES) ? g_c[rlo] : 0.f;
        float chi = (rhi < N_NODES) ? g_c[rhi] : 0.f;
#pragma unroll
        for (int nf = 0; nf < 8; ++nf) {
            int n = n0 + wn * 64 + nf * 8 + (lane & 3) * 2;
            float b0 = __ldg(bm + n), b1 = __ldg(bm + n + 1);
            int j = mt * 32 + nf * 4;
            stash[(j + 0) * 256 + tid] = acc[mt][nf][0] + clo * b0;
            stash[(j + 1) * 256 + tid] = acc[mt][nf][1] + clo * b1;
            stash[(j + 2) * 256 + tid] = acc[mt][nf][2] + chi * b0;
            stash[(j + 3) * 256 + tid] = acc[mt][nf][3] + chi * b1;
        }
    }

#pragma unroll
    for (int i = 0; i < 2; ++i)
#pragma unroll
        for (int j = 0; j < 8; ++j)
#pragma unroll
            for (int q = 0; q < 4; ++q) acc[i][j][q] = 0.f;

    // ---- branch 1: scale GEMM over g_B / Ws ----
    gemm_tiles<F_HEDGE>(g_B, g_Ws_hi, g_Ws_lo, sm, smb, r0, n0, tid,
                        aAh0, aAl0, aBh0, aBl0, acc);

    // ---- combine epilogue ----
#pragma unroll
    for (int mt = 0; mt < 2; ++mt) {
        int rlo = r0 + wm * 32 + mt * 16 + (lane >> 2);
        int rhi = rlo + 8;
        float clo = (rlo < N_NODES) ? g_c2[rlo] : 0.f;
        float chi = (rhi < N_NODES) ? g_c2[rhi] : 0.f;
#pragma unroll
        for (int nf = 0; nf < 8; ++nf) {
            int n = n0 + wn * 64 + nf * 8 + (lane & 3) * 2;
            float b0 = __ldg(bs + n), b1 = __ldg(bs + n + 1);
            int j = mt * 32 + nf * 4;
            float m0 = stash[(j + 0) * 256 + tid];
            float m1 = stash[(j + 1) * 256 + tid];
            float m2 = stash[(j + 2) * 256 + tid];
            float m3 = stash[(j + 3) * 256 + tid];
            if (rlo < N_NODES)
                *reinterpret_cast<float2*>(out + (size_t)rlo * 256 + n) =
                    make_float2((acc[mt][nf][0] + clo * b0) * m0,
                                (acc[mt][nf][1] + clo * b1) * m1);
            if (rhi < N_NODES)
                *reinterpret_cast<float2*>(out + (size_t)rhi * 256 + n) =
                    make_float2((acc[mt][nf][2] + chi * b0) * m2,
                                (acc[mt][nf][3] + chi * b1) * m3);
        }
    }
}

// ---------------------------------------------------------------------------
extern "C" void kernel_launch(void* const* d_in, const int* in_sizes, int n_in,
                              void* d_out, int out_size)
{
    const float* node_features  = (const float*)d_in[0];
    const float* hedge_features = (const float*)d_in[1];
    const int*   node_senders   = (const int*)d_in[2];
    const int*   node_receivers = (const int*)d_in[3];
    const float* node_conv      = (const float*)d_in[4];
    const int*   h_senders      = (const int*)d_in[5];
    const int*   h_receivers    = (const int*)d_in[6];
    const float* h_conv         = (const float*)d_in[7];
    const float* W_msg          = (const float*)d_in[8];
    const float* b_msg          = (const float*)d_in[9];
    const float* W_scale        = (const float*)d_in[10];
    const float* b_scale        = (const float*)d_in[11];
    float* out = (float*)d_out;

    const int nE  = in_sizes[2];
    const int nE2 = in_sizes[5];

    cudaFuncSetAttribute(gemm_fused, cudaFuncAttributeMaxDynamicSharedMemorySize, SMEM_BYTES);

    prep<<<1280, 256>>>(W_msg, W_scale);
    scatter_seg<256, 128><<<(nE + 511) / 512, 256>>>(
        node_features, node_senders, node_receivers, node_conv, nE);
    scatter_seg<128, 128><<<(nE2 + 1023) / 1024, 256>>>(
        hedge_features, h_senders, h_receivers, h_conv, nE2);

    dim3 grid((N_NODES + 127) / 128, 2);
    gemm_fused<<<grid, 256, SMEM_BYTES>>>(b_msg, b_scale, out);
}